// round 3
// baseline (speedup 1.0000x reference)
#include <cuda_runtime.h>
#include <cuda.h>
#include <cstdint>
#include <cstdio>

// ============================================================================
// Arch-feature dispatch: tcgen05 only exists in compute_103a/sm_103a passes.
// Non-'a' passes (compute_103 PTX for JIT fallback) get a legacy int8
// mma.sync implementation instead. Each device pass compiles ONE consistent
// pipeline; the runtime loads the best-matching cubin.
// ============================================================================
#if defined(__CUDA_ARCH__) && (defined(__CUDA_ARCH_FEAT_SM103_ALL) || defined(__CUDA_ARCH_FEAT_SM100_ALL))
#define USE_TCGEN05 1
#else
#define USE_TCGEN05 0
#endif

// ============================================================================
// Problem constants
// ============================================================================
#define K_DIM 12288
#define BROWS 8192
#define COUT  1000
#define CPAD  1024

// GEMM tiling (tcgen05 path)
#define M_TILE 128
#define N_TILE 256
#define K_TILE 128                    // bytes of K per pipeline stage
#define STAGES 4
#define K_ITERS (K_DIM / K_TILE)      // 96
#define A_STAGE_BYTES (M_TILE * K_TILE)               // 16384
#define B_STAGE_BYTES (N_TILE * K_TILE)               // 32768
#define STAGE_BYTES   (A_STAGE_BYTES + B_STAGE_BYTES) // 49152

// SMEM layout (tcgen05 path)
#define SMEM_TMEM_PTR 0
#define SMEM_FULL(s)  (16 + (s) * 8)
#define SMEM_EMPTY(s) (16 + STAGES * 8 + (s) * 8)
#define SMEM_DONE     (16 + 2 * STAGES * 8)
#define SMEM_DATA     1024
#define SMEM_BYTES    (SMEM_DATA + STAGES * STAGE_BYTES)   // 197632

// TMEM layout: D = cols [0,256), unit scales at [256,288)
#define TMEM_D    0
#define TMEM_SCA  256
#define TMEM_SCB  260
#define TMEM_COLS 512

// idesc: kind::mxf8f6f4, E4M3 x E4M3, M=128 -> bit27, UE8M0 bit23, N/8 bits17-22
#define MMA_IDESC ((1u << 27) | (1u << 23) | ((N_TILE / 8u) << 17))

// Fallback tiling constants
#define FB_NIT    (K_DIM / 32)          // 384 k-chunks of 32 bytes
#define FB_A_ST   (128 * 48)            // 6144 B (48B pitch: 32B data + 16B pad)
#define FB_STAGE  (FB_A_ST + 256 * 48)  // 18432 B

// ============================================================================
// Scratch (alloc-free rule: __device__ globals)
// ============================================================================
__device__ __align__(1024) unsigned char g_A[(size_t)BROWS * K_DIM];  // sign(input)
__device__ __align__(1024) unsigned char g_W[(size_t)CPAD * K_DIM];   // sign(weight), pad rows zero

// ============================================================================
// Generic PTX helpers
// ============================================================================
__device__ __forceinline__ uint32_t smem_u32(const void* p) {
    uint32_t a;
    asm("{ .reg .u64 t; cvta.to.shared.u64 t, %1; cvt.u32.u64 %0, t; }" : "=r"(a) : "l"(p));
    return a;
}

#if USE_TCGEN05
__device__ __forceinline__ uint32_t elect_one_pred() {
    uint32_t p;
    asm volatile("{\n\t.reg .pred p;\n\telect.sync _|p, 0xFFFFFFFF;\n\tselp.b32 %0, 1, 0, p;\n\t}" : "=r"(p));
    return p;
}

#define MBARRIER_INIT(addr, cnt) \
    asm volatile("mbarrier.init.shared.b64 [%0], %1;" :: "r"((uint32_t)(addr)), "r"((uint32_t)(cnt)) : "memory")
#define MBARRIER_EXPECT_TX(addr, bytes) \
    asm volatile("mbarrier.arrive.expect_tx.shared.b64 _, [%0], %1;" :: "r"((uint32_t)(addr)), "r"((uint32_t)(bytes)) : "memory")

#define MBARRIER_WAIT_PARITY(mbar_smem_addr, phase_parity) do { \
    uint32_t _mbar = (uint32_t)(mbar_smem_addr); \
    uint32_t _parity = (uint32_t)(phase_parity); \
    uint32_t _done; \
    asm volatile( \
        "{\n\t.reg .pred p;\n\t" \
        "mbarrier.try_wait.parity.acquire.cta.shared::cta.b64 p, [%1], %2;\n\t" \
        "selp.b32 %0, 1, 0, p;\n\t}" \
        : "=r"(_done) : "r"(_mbar), "r"(_parity) : "memory"); \
    if (!_done) { \
        asm volatile( \
            "{\n\t.reg .pred P1;\n\t" \
            "WAIT_LOOP_%=:\n\t" \
            "mbarrier.try_wait.parity.acquire.cta.shared::cta.b64 P1, [%0], %1, 0x989680;\n\t" \
            "@P1 bra.uni WAIT_DONE_%=;\n\t" \
            "bra.uni WAIT_LOOP_%=;\n\t" \
            "WAIT_DONE_%=:\n\t}" \
            :: "r"(_mbar), "r"(_parity) : "memory"); \
    } \
} while (0)

#define TCGEN05_ALLOC(smem_addr, n) \
    asm volatile("tcgen05.alloc.cta_group::1.sync.aligned.shared::cta.b32 [%0], %1;" \
                 :: "r"((uint32_t)(smem_addr)), "r"((uint32_t)(n)) : "memory")
#define TCGEN05_DEALLOC(tmem, n) \
    asm volatile("tcgen05.dealloc.cta_group::1.sync.aligned.b32 %0, %1;" :: "r"(tmem), "r"((uint32_t)(n)))
#define TCGEN05_RELINQUISH() \
    asm volatile("tcgen05.relinquish_alloc_permit.cta_group::1.sync.aligned;")
#define TCGEN05_COMMIT(mbar) \
    asm volatile("tcgen05.commit.cta_group::1.mbarrier::arrive::one.shared::cluster.b64 [%0];" \
                 :: "r"((uint32_t)(mbar)) : "memory")
#define TCGEN05_WAIT_ST() asm volatile("tcgen05.wait::st.sync.aligned;" ::: "memory")
#define TCGEN05_WAIT_LD() asm volatile("tcgen05.wait::ld.sync.aligned;" ::: "memory")
#define TCGEN05_FENCE_BEFORE() asm volatile("tcgen05.fence::before_thread_sync;" ::: "memory")
#define TCGEN05_FENCE_AFTER()  asm volatile("tcgen05.fence::after_thread_sync;" ::: "memory")

#define TCGEN05_ST_32X32B_X1(tmem_addr, r0) \
    asm volatile("tcgen05.st.sync.aligned.32x32b.x1.b32 [%0], {%1};" :: "r"(tmem_addr), "r"(r0) : "memory")

#define TCGEN05_LD_32X32B_X32(r, tmem_addr) \
    asm volatile( \
        "tcgen05.ld.sync.aligned.32x32b.x32.b32 " \
        "{%0, %1, %2, %3, %4, %5, %6, %7, " \
        " %8, %9, %10, %11, %12, %13, %14, %15, " \
        " %16, %17, %18, %19, %20, %21, %22, %23, " \
        " %24, %25, %26, %27, %28, %29, %30, %31}, [%32];" \
        : "=r"((r)[0]),  "=r"((r)[1]),  "=r"((r)[2]),  "=r"((r)[3]), \
          "=r"((r)[4]),  "=r"((r)[5]),  "=r"((r)[6]),  "=r"((r)[7]), \
          "=r"((r)[8]),  "=r"((r)[9]),  "=r"((r)[10]), "=r"((r)[11]), \
          "=r"((r)[12]), "=r"((r)[13]), "=r"((r)[14]), "=r"((r)[15]), \
          "=r"((r)[16]), "=r"((r)[17]), "=r"((r)[18]), "=r"((r)[19]), \
          "=r"((r)[20]), "=r"((r)[21]), "=r"((r)[22]), "=r"((r)[23]), \
          "=r"((r)[24]), "=r"((r)[25]), "=r"((r)[26]), "=r"((r)[27]), \
          "=r"((r)[28]), "=r"((r)[29]), "=r"((r)[30]), "=r"((r)[31]) \
        : "r"(tmem_addr))

// SMEM descriptor: SW128, Blackwell version=1, LBO=1, SBO=64 (K-major 128B rows)
static constexpr uint64_t SMEM_DESC_BASE_SW128 =
    (uint64_t(2) << 61) | (uint64_t(1) << 46) | (uint64_t(64) << 32) | (uint64_t(1) << 16);
#define MAKE_SMEM_DESC(base_addr) (SMEM_DESC_BASE_SW128 | ((uint64_t)((base_addr) >> 4) & 0x3FFF))

__device__ __forceinline__ void tma_load_2d(uint32_t smem_addr, const void* map,
                                            int cx, int cy, uint32_t mbar) {
    asm volatile(
        "cp.async.bulk.tensor.2d.shared::cta.global.tile.mbarrier::complete_tx::bytes "
        "[%0], [%1, {%2, %3}], [%4];"
        :: "r"(smem_addr), "l"(map), "r"(cx), "r"(cy), "r"(mbar) : "memory");
}

__device__ __forceinline__ void mma_mxf8_ss(uint32_t d_tmem, uint64_t a_desc, uint64_t b_desc,
                                            uint32_t idesc, uint32_t sfa, uint32_t sfb, bool acc) {
    uint32_t en = acc ? 1u : 0u;
    asm volatile(
        "{\n\t.reg .pred p;\n\t"
        "setp.ne.u32 p, %6, 0;\n\t"
        "tcgen05.mma.cta_group::1.kind::mxf8f6f4.block_scale.scale_vec::1X "
        "[%0], %1, %2, %3, [%4], [%5], p;\n\t}"
        :: "r"(d_tmem), "l"(a_desc), "l"(b_desc), "r"(idesc),
           "r"(sfa), "r"(sfb), "r"(en) : "memory");
}
#else  // !USE_TCGEN05 — legacy path helpers (valid on plain compute_103)

__device__ __forceinline__ void ldsm_x4(uint32_t* r, uint32_t addr) {
    asm volatile("ldmatrix.sync.aligned.m8n8.x4.shared.b16 {%0,%1,%2,%3}, [%4];"
        : "=r"(r[0]), "=r"(r[1]), "=r"(r[2]), "=r"(r[3]) : "r"(addr));
}
__device__ __forceinline__ void ldsm_x2(uint32_t* r, uint32_t addr) {
    asm volatile("ldmatrix.sync.aligned.m8n8.x2.shared.b16 {%0,%1}, [%2];"
        : "=r"(r[0]), "=r"(r[1]) : "r"(addr));
}
__device__ __forceinline__ void mma_s8(int* c, const uint32_t* a, const uint32_t* b) {
    asm volatile("mma.sync.aligned.m16n8k32.row.col.s32.s8.s8.s32 "
        "{%0,%1,%2,%3}, {%4,%5,%6,%7}, {%8,%9}, {%0,%1,%2,%3};"
        : "+r"(c[0]), "+r"(c[1]), "+r"(c[2]), "+r"(c[3])
        : "r"(a[0]), "r"(a[1]), "r"(a[2]), "r"(a[3]), "r"(b[0]), "r"(b[1]));
}
__device__ __forceinline__ void cp_async16(uint32_t dst, const void* src) {
    asm volatile("cp.async.cg.shared.global [%0], [%1], 16;" :: "r"(dst), "l"(src));
}
#endif

// ============================================================================
// Binarize: fp32 -> sign byte. tcgen05 pass: e4m3 (+1=0x38, -1=0xB8, 0=0x00).
// fallback pass: s8 (+1=0x01, -1=0xFF, 0=0x00).
// ============================================================================
__device__ __forceinline__ unsigned char sign_byte(float x) {
#if USE_TCGEN05
    return (x == 0.0f) ? 0u : (unsigned char)(0x38u | ((__float_as_uint(x) >> 24) & 0x80u));
#else
    return (x == 0.0f) ? 0u : ((__float_as_uint(x) & 0x80000000u) ? 0xFFu : 0x01u);
#endif
}

__global__ void binarize_input_kernel(const float4* __restrict__ in, uchar4* __restrict__ out, int n4) {
    int i = blockIdx.x * blockDim.x + threadIdx.x;
    if (i >= n4) return;
    float4 v = in[i];
    uchar4 o;
    o.x = sign_byte(v.x); o.y = sign_byte(v.y); o.z = sign_byte(v.z); o.w = sign_byte(v.w);
    out[i] = o;
}

__global__ void binarize_weight_kernel(const float4* __restrict__ w, uchar4* __restrict__ out, int n4) {
    int i = blockIdx.x * blockDim.x + threadIdx.x;
    if (i >= n4) return;
    int row = i / (K_DIM / 4);
    uchar4 o;
    if (row < COUT) {
        float4 v = w[i];
        o.x = sign_byte(v.x); o.y = sign_byte(v.y); o.z = sign_byte(v.z); o.w = sign_byte(v.w);
    } else {
        o.x = o.y = o.z = o.w = 0;  // padded N rows contribute 0
    }
    out[i] = o;
}

// ============================================================================
// GEMM kernel. One name, two per-arch bodies.
// Grid (CPAD/N_TILE, BROWS/M_TILE) = (4, 64). 256 threads.
// ============================================================================
__global__ __launch_bounds__(256, 1) void binary_gemm_kernel(
    float* __restrict__ out,
    const unsigned char* __restrict__ Ag,
    const unsigned char* __restrict__ Wg,
    const __grid_constant__ CUtensorMap tma_a,
    const __grid_constant__ CUtensorMap tma_b)
{
#if USE_TCGEN05
    // ------------------------------------------------------------------
    // tcgen05 mxf8 SS, warp-specialized 4-stage TMA pipeline.
    // warps 0-3: scale init + epilogue. warp 4: TMA producer. warp 5: MMA.
    // ------------------------------------------------------------------
    extern __shared__ char smem[];
    uint32_t sb = smem_u32(smem);
    int tid = threadIdx.x;
    int wid = tid >> 5;
    int lane = tid & 31;
    int nblk = blockIdx.x;
    int mblk = blockIdx.y;

    if (wid == 5) TCGEN05_ALLOC(sb + SMEM_TMEM_PTR, TMEM_COLS);
    __syncthreads();
    uint32_t tmem;
    asm volatile("ld.shared.b32 %0, [%1];" : "=r"(tmem) : "r"(sb + SMEM_TMEM_PTR));

    if (tid == 0) {
        for (int s = 0; s < STAGES; s++) {
            MBARRIER_INIT(sb + SMEM_FULL(s), 1);
            MBARRIER_INIT(sb + SMEM_EMPTY(s), 1);
        }
        MBARRIER_INIT(sb + SMEM_DONE, 1);
    }

    // Unit scales (ue8m0 0x7F = 1.0) in cols [256,288), every subpartition.
    if (wid < 4) {
        uint32_t woff = (uint32_t)wid << 21;
        const uint32_t ones = 0x7F7F7F7Fu;
        for (int c = 0; c < 32; c++) {
            TCGEN05_ST_32X32B_X1(tmem + 256 + c + woff, ones);
        }
        TCGEN05_WAIT_ST();
        TCGEN05_FENCE_BEFORE();
    }
    __syncthreads();

    if (wid == 4) {
        uint32_t el = elect_one_pred();
        int s = 0, ph = 1;
        for (int it = 0; it < K_ITERS; ++it) {
            MBARRIER_WAIT_PARITY(sb + SMEM_EMPTY(s), ph);
            if (el) {
                uint32_t full = sb + SMEM_FULL(s);
                MBARRIER_EXPECT_TX(full, STAGE_BYTES);
                uint32_t a_dst = sb + SMEM_DATA + s * STAGE_BYTES;
                tma_load_2d(a_dst, &tma_a, it * K_TILE, mblk * M_TILE, full);
                tma_load_2d(a_dst + A_STAGE_BYTES, &tma_b, it * K_TILE, nblk * N_TILE, full);
            }
            if (++s == STAGES) { s = 0; ph ^= 1; }
        }
    } else if (wid == 5) {
        TCGEN05_FENCE_AFTER();
        uint32_t el = elect_one_pred();
        int s = 0, ph = 0;
        for (int it = 0; it < K_ITERS; ++it) {
            MBARRIER_WAIT_PARITY(sb + SMEM_FULL(s), ph);
            if (el) {
                uint32_t a_base = sb + SMEM_DATA + s * STAGE_BYTES;
                uint64_t ad = MAKE_SMEM_DESC(a_base);
                uint64_t bd = MAKE_SMEM_DESC(a_base + A_STAGE_BYTES);
                #pragma unroll
                for (int k = 0; k < 4; k++) {
                    mma_mxf8_ss(tmem + TMEM_D, ad + k * 2, bd + k * 2, MMA_IDESC,
                                tmem + TMEM_SCA, tmem + TMEM_SCB,
                                !(it == 0 && k == 0));
                }
                TCGEN05_COMMIT(sb + SMEM_EMPTY(s));
            }
            if (++s == STAGES) { s = 0; ph ^= 1; }
        }
        if (el) TCGEN05_COMMIT(sb + SMEM_DONE);
    }

    if (wid < 4) {
        MBARRIER_WAIT_PARITY(sb + SMEM_DONE, 0);
        TCGEN05_FENCE_AFTER();

        int m = mblk * M_TILE + wid * 32 + lane;
        float* orow = out + (size_t)m * COUT;
        int nbase = nblk * N_TILE;

        for (int c0 = 0; c0 < N_TILE; c0 += 32) {
            uint32_t r[32];
            TCGEN05_LD_32X32B_X32(r, tmem + TMEM_D + c0);
            TCGEN05_WAIT_LD();
            TCGEN05_FENCE_BEFORE();
            #pragma unroll
            for (int j = 0; j < 32; j += 4) {
                int n = nbase + c0 + j;
                if (n < COUT) {  // COUT % 4 == 0: whole float4 valid
                    float4 v = make_float4(__uint_as_float(r[j]), __uint_as_float(r[j + 1]),
                                           __uint_as_float(r[j + 2]), __uint_as_float(r[j + 3]));
                    *reinterpret_cast<float4*>(orow + n) = v;
                }
            }
        }
    }

    __syncthreads();
    if (wid == 5) {
        TCGEN05_RELINQUISH();
        TCGEN05_DEALLOC(tmem, TMEM_COLS);
    }
#else
    // ------------------------------------------------------------------
    // Fallback: legacy int8 mma.sync.m16n8k32, cp.async double buffering.
    // 8 warps (2x4), each computes a 64x64 sub-tile. 48B-pitch smem rows
    // make all ldmatrix reads bank-conflict free.
    // ------------------------------------------------------------------
    extern __shared__ char smem[];
    uint32_t sb = smem_u32(smem);
    const int tid = threadIdx.x, lane = tid & 31, wid = tid >> 5;
    const int nblk = blockIdx.x, mblk = blockIdx.y;
    const int wm = wid >> 2, wn = wid & 3;

    int c[4][8][4];
    #pragma unroll
    for (int mi = 0; mi < 4; mi++)
        #pragma unroll
        for (int ni = 0; ni < 8; ni++)
            #pragma unroll
            for (int j = 0; j < 4; j++) c[mi][ni][j] = 0;

    // Prefetch k-chunk `it` into stage `s`
    auto prefetch = [&](int it, int s) {
        int kb = it * 32;
        #pragma unroll
        for (int t = 0; t < 3; t++) {
            int idx = tid + t * 256;
            uint32_t dst;
            const unsigned char* src;
            if (idx < 256) {
                int r = idx >> 1, ch = idx & 1;
                dst = sb + s * FB_STAGE + (r * 3 + ch) * 16;
                src = Ag + (size_t)(mblk * 128 + r) * K_DIM + kb + ch * 16;
            } else {
                int j = idx - 256;
                int r = j >> 1, ch = j & 1;
                dst = sb + s * FB_STAGE + FB_A_ST + (r * 3 + ch) * 16;
                src = Wg + (size_t)(nblk * 256 + r) * K_DIM + kb + ch * 16;
            }
            cp_async16(dst, src);
        }
        asm volatile("cp.async.commit_group;" ::: "memory");
    };

    prefetch(0, 0);
    for (int it = 0; it < FB_NIT; ++it) {
        __syncthreads();
        if (it + 1 < FB_NIT) {
            prefetch(it + 1, (it + 1) & 1);
            asm volatile("cp.async.wait_group 1;" ::: "memory");
        } else {
            asm volatile("cp.async.wait_group 0;" ::: "memory");
        }
        __syncthreads();

        int s = it & 1;
        uint32_t aB = sb + s * FB_STAGE;
        uint32_t bB = aB + FB_A_ST;

        uint32_t afr[4][4], bfr[8][2];
        #pragma unroll
        for (int mi = 0; mi < 4; mi++) {
            int row = wm * 64 + mi * 16 + (lane & 15);
            int ch = lane >> 4;
            ldsm_x4(afr[mi], aB + (row * 3 + ch) * 16);
        }
        #pragma unroll
        for (int ni = 0; ni < 8; ni++) {
            int row = wn * 64 + ni * 8 + (lane & 7);
            int ch = (lane >> 3) & 1;  // lanes 0-15 meaningful for x2
            ldsm_x2(bfr[ni], bB + (row * 3 + ch) * 16);
        }
        #pragma unroll
        for (int mi = 0; mi < 4; mi++)
            #pragma unroll
            for (int ni = 0; ni < 8; ni++)
                mma_s8(c[mi][ni], afr[mi], bfr[ni]);
    }

    // Epilogue: s32 -> f32 (exact; |acc| <= 12288)
    int g = lane >> 2, tig = lane & 3;
    #pragma unroll
    for (int mi = 0; mi < 4; mi++) {
        int m0 = mblk * 128 + wm * 64 + mi * 16 + g;
        #pragma unroll
        for (int ni = 0; ni < 8; ni++) {
            int n0 = nblk * 256 + wn * 64 + ni * 8 + tig * 2;
            if (n0 < COUT) {
                out[(size_t)m0 * COUT + n0]       = (float)c[mi][ni][0];
                out[(size_t)(m0 + 8) * COUT + n0] = (float)c[mi][ni][2];
            }
            if (n0 + 1 < COUT) {
                out[(size_t)m0 * COUT + n0 + 1]       = (float)c[mi][ni][1];
                out[(size_t)(m0 + 8) * COUT + n0 + 1] = (float)c[mi][ni][3];
            }
        }
    }
#endif
}

// ============================================================================
// Host launch
// ============================================================================
typedef CUresult (*PFN_TMapEncode)(
    CUtensorMap*, CUtensorMapDataType, cuuint32_t, void*,
    const cuuint64_t*, const cuuint64_t*, const cuuint32_t*, const cuuint32_t*,
    CUtensorMapInterleave, CUtensorMapSwizzle, CUtensorMapL2promotion, CUtensorMapFloatOOBfill);

extern "C" void kernel_launch(void* const* d_in, const int* in_sizes, int n_in,
                              void* d_out, int out_size) {
    const float* inp = (const float*)d_in[0];
    const float* wgt = (const float*)d_in[1];
    if (in_sizes[0] == COUT * K_DIM) { inp = (const float*)d_in[1]; wgt = (const float*)d_in[0]; }
    float* out = (float*)d_out;

    void* pA = nullptr;
    void* pW = nullptr;
    cudaGetSymbolAddress(&pA, g_A);
    cudaGetSymbolAddress(&pW, g_W);

    // 1) binarize
    {
        int n4 = (BROWS * K_DIM) / 4;
        binarize_input_kernel<<<(n4 + 255) / 256, 256>>>((const float4*)inp, (uchar4*)pA, n4);
    }
    {
        int n4 = (CPAD * K_DIM) / 4;
        binarize_weight_kernel<<<(n4 + 255) / 256, 256>>>((const float4*)wgt, (uchar4*)pW, n4);
    }

    // 2) TMA descriptors (used only by the tcgen05 cubin; harmless otherwise)
    PFN_TMapEncode enc = nullptr;
    {
        void* fp = nullptr;
        cudaDriverEntryPointQueryResult st;
        cudaGetDriverEntryPointByVersion("cuTensorMapEncodeTiled", &fp, 12000,
                                         cudaEnableDefault, &st);
        enc = (PFN_TMapEncode)fp;
    }

    CUtensorMap mapA, mapB;
    if (enc) {
        {
            cuuint64_t dims[2] = {K_DIM, BROWS};
            cuuint64_t str[1] = {K_DIM};
            cuuint32_t box[2] = {K_TILE, M_TILE};
            cuuint32_t es[2] = {1, 1};
            enc(&mapA, CU_TENSOR_MAP_DATA_TYPE_UINT8, 2, pA, dims, str, box, es,
                CU_TENSOR_MAP_INTERLEAVE_NONE, CU_TENSOR_MAP_SWIZZLE_128B,
                CU_TENSOR_MAP_L2_PROMOTION_L2_128B, CU_TENSOR_MAP_FLOAT_OOB_FILL_NONE);
        }
        {
            cuuint64_t dims[2] = {K_DIM, CPAD};
            cuuint64_t str[1] = {K_DIM};
            cuuint32_t box[2] = {K_TILE, N_TILE};
            cuuint32_t es[2] = {1, 1};
            enc(&mapB, CU_TENSOR_MAP_DATA_TYPE_UINT8, 2, pW, dims, str, box, es,
                CU_TENSOR_MAP_INTERLEAVE_NONE, CU_TENSOR_MAP_SWIZZLE_128B,
                CU_TENSOR_MAP_L2_PROMOTION_L2_128B, CU_TENSOR_MAP_FLOAT_OOB_FILL_NONE);
        }
    }

    // 3) GEMM
    cudaFuncSetAttribute(binary_gemm_kernel, cudaFuncAttributeMaxDynamicSharedMemorySize, SMEM_BYTES);
    dim3 grid(CPAD / N_TILE, BROWS / M_TILE, 1);  // (4, 64)
    binary_gemm_kernel<<<grid, 256, SMEM_BYTES>>>(out, (const unsigned char*)pA,
                                                  (const unsigned char*)pW, mapA, mapB);
}

// round 6
// speedup vs baseline: 1.0743x; 1.0743x over previous
#include <cuda_runtime.h>
#include <cuda.h>
#include <cstdint>
#include <cstdio>

// ============================================================================
// Arch-feature dispatch: tcgen05 only exists in compute_103a/sm_103a passes.
// ============================================================================
#if defined(__CUDA_ARCH__) && (defined(__CUDA_ARCH_FEAT_SM103_ALL) || defined(__CUDA_ARCH_FEAT_SM100_ALL))
#define USE_TCGEN05 1
#else
#define USE_TCGEN05 0
#endif

// ============================================================================
// Problem constants
// ============================================================================
#define K_DIM 12288
#define BROWS 8192
#define COUT  1000
#define CPAD  1024

// GEMM tiling (tcgen05 path)
#define M_TILE 128
#define N_TILE 256
#define K_TILE 128
#define STAGES 4
#define K_ITERS (K_DIM / K_TILE)      // 96
#define A_STAGE_BYTES (M_TILE * K_TILE)               // 16384
#define B_STAGE_BYTES (N_TILE * K_TILE)               // 32768
#define STAGE_BYTES   (A_STAGE_BYTES + B_STAGE_BYTES) // 49152

// Cluster: 4 CTAs along mblk share the B tile via TMA multicast slicing
#define CLUSTER_Y 4
#define B_SLICE_ROWS (N_TILE / CLUSTER_Y)             // 64
#define B_SLICE_BYTES (B_SLICE_ROWS * K_TILE)         // 8192
#define MCAST_MASK 0xFu

// SMEM layout (tcgen05 path)
#define SMEM_TMEM_PTR 0
#define SMEM_FULL(s)  (16 + (s) * 8)
#define SMEM_EMPTY(s) (16 + STAGES * 8 + (s) * 8)
#define SMEM_DONE     (16 + 2 * STAGES * 8)
#define SMEM_DATA     1024
#define SMEM_BYTES    (SMEM_DATA + STAGES * STAGE_BYTES)   // 197632

// TMEM layout
#define TMEM_D    0
#define TMEM_SCA  256
#define TMEM_SCB  260
#define TMEM_COLS 512

#define MMA_IDESC ((1u << 27) | (1u << 23) | ((N_TILE / 8u) << 17))

// Fallback tiling constants
#define FB_NIT    (K_DIM / 32)
#define FB_A_ST   (128 * 48)
#define FB_STAGE  (FB_A_ST + 256 * 48)

// Binarize constants (fused kernel; each thread = 16 elements, 1x uint4 store)
#define N4A ((BROWS * K_DIM) / 4)     // 25,165,824 float4s in input
#define N4W ((CPAD * K_DIM) / 4)      //  3,145,728 float4s in (padded) weight
#define NT_A (N4A / 4)                //  6,291,456 threads for A
#define NT_W (N4W / 4)                //    786,432 threads for W
#define NT_TOTAL (NT_A + NT_W)        //  7,077,888
#define BIN_THREADS 256
#define BIN_BLOCKS (NT_TOTAL / BIN_THREADS)  // 27648 exactly
#define W_T_PER_ROW (K_DIM / 16)      // 768 threads per weight row

// ============================================================================
// Scratch (alloc-free rule: __device__ globals)
// ============================================================================
__device__ __align__(1024) unsigned char g_A[(size_t)BROWS * K_DIM];
__device__ __align__(1024) unsigned char g_W[(size_t)CPAD * K_DIM];

// ============================================================================
// Generic PTX helpers
// ============================================================================
__device__ __forceinline__ uint32_t smem_u32(const void* p) {
    uint32_t a;
    asm("{ .reg .u64 t; cvta.to.shared.u64 t, %1; cvt.u32.u64 %0, t; }" : "=r"(a) : "l"(p));
    return a;
}

#if USE_TCGEN05
__device__ __forceinline__ uint32_t elect_one_pred() {
    uint32_t p;
    asm volatile("{\n\t.reg .pred p;\n\telect.sync _|p, 0xFFFFFFFF;\n\tselp.b32 %0, 1, 0, p;\n\t}" : "=r"(p));
    return p;
}
__device__ __forceinline__ uint32_t cluster_rank() {
    uint32_t r;
    asm("mov.u32 %0, %%cluster_ctarank;" : "=r"(r));
    return r;
}

#define CLUSTER_SYNC() do { \
    asm volatile("barrier.cluster.arrive.aligned;" ::: "memory"); \
    asm volatile("barrier.cluster.wait.aligned;" ::: "memory"); \
} while (0)

#define MBARRIER_INIT(addr, cnt) \
    asm volatile("mbarrier.init.shared.b64 [%0], %1;" :: "r"((uint32_t)(addr)), "r"((uint32_t)(cnt)) : "memory")
#define MBARRIER_EXPECT_TX(addr, bytes) \
    asm volatile("mbarrier.arrive.expect_tx.shared.b64 _, [%0], %1;" :: "r"((uint32_t)(addr)), "r"((uint32_t)(bytes)) : "memory")

#define MBARRIER_WAIT_PARITY(mbar_smem_addr, phase_parity) do { \
    uint32_t _mbar = (uint32_t)(mbar_smem_addr); \
    uint32_t _parity = (uint32_t)(phase_parity); \
    uint32_t _done; \
    asm volatile( \
        "{\n\t.reg .pred p;\n\t" \
        "mbarrier.try_wait.parity.acquire.cta.shared::cta.b64 p, [%1], %2;\n\t" \
        "selp.b32 %0, 1, 0, p;\n\t}" \
        : "=r"(_done) : "r"(_mbar), "r"(_parity) : "memory"); \
    if (!_done) { \
        asm volatile( \
            "{\n\t.reg .pred P1;\n\t" \
            "WAIT_LOOP_%=:\n\t" \
            "mbarrier.try_wait.parity.acquire.cta.shared::cta.b64 P1, [%0], %1, 0x989680;\n\t" \
            "@P1 bra.uni WAIT_DONE_%=;\n\t" \
            "bra.uni WAIT_LOOP_%=;\n\t" \
            "WAIT_DONE_%=:\n\t}" \
            :: "r"(_mbar), "r"(_parity) : "memory"); \
    } \
} while (0)

#define TCGEN05_ALLOC(smem_addr, n) \
    asm volatile("tcgen05.alloc.cta_group::1.sync.aligned.shared::cta.b32 [%0], %1;" \
                 :: "r"((uint32_t)(smem_addr)), "r"((uint32_t)(n)) : "memory")
#define TCGEN05_DEALLOC(tmem, n) \
    asm volatile("tcgen05.dealloc.cta_group::1.sync.aligned.b32 %0, %1;" :: "r"(tmem), "r"((uint32_t)(n)))
#define TCGEN05_RELINQUISH() \
    asm volatile("tcgen05.relinquish_alloc_permit.cta_group::1.sync.aligned;")
#define TCGEN05_COMMIT(mbar) \
    asm volatile("tcgen05.commit.cta_group::1.mbarrier::arrive::one.shared::cluster.b64 [%0];" \
                 :: "r"((uint32_t)(mbar)) : "memory")
#define TCGEN05_COMMIT_MC(mbar, mask) \
    asm volatile("tcgen05.commit.cta_group::1.mbarrier::arrive::one.shared::cluster.multicast::cluster.b64 [%0], %1;" \
                 :: "r"((uint32_t)(mbar)), "h"((uint16_t)(mask)) : "memory")
#define TCGEN05_WAIT_ST() asm volatile("tcgen05.wait::st.sync.aligned;" ::: "memory")
#define TCGEN05_WAIT_LD() asm volatile("tcgen05.wait::ld.sync.aligned;" ::: "memory")
#define TCGEN05_FENCE_BEFORE() asm volatile("tcgen05.fence::before_thread_sync;" ::: "memory")
#define TCGEN05_FENCE_AFTER()  asm volatile("tcgen05.fence::after_thread_sync;" ::: "memory")

#define TCGEN05_ST_32X32B_X1(tmem_addr, r0) \
    asm volatile("tcgen05.st.sync.aligned.32x32b.x1.b32 [%0], {%1};" :: "r"(tmem_addr), "r"(r0) : "memory")

#define TCGEN05_LD_32X32B_X32(r, tmem_addr) \
    asm volatile( \
        "tcgen05.ld.sync.aligned.32x32b.x32.b32 " \
        "{%0, %1, %2, %3, %4, %5, %6, %7, " \
        " %8, %9, %10, %11, %12, %13, %14, %15, " \
        " %16, %17, %18, %19, %20, %21, %22, %23, " \
        " %24, %25, %26, %27, %28, %29, %30, %31}, [%32];" \
        : "=r"((r)[0]),  "=r"((r)[1]),  "=r"((r)[2]),  "=r"((r)[3]), \
          "=r"((r)[4]),  "=r"((r)[5]),  "=r"((r)[6]),  "=r"((r)[7]), \
          "=r"((r)[8]),  "=r"((r)[9]),  "=r"((r)[10]), "=r"((r)[11]), \
          "=r"((r)[12]), "=r"((r)[13]), "=r"((r)[14]), "=r"((r)[15]), \
          "=r"((r)[16]), "=r"((r)[17]), "=r"((r)[18]), "=r"((r)[19]), \
          "=r"((r)[20]), "=r"((r)[21]), "=r"((r)[22]), "=r"((r)[23]), \
          "=r"((r)[24]), "=r"((r)[25]), "=r"((r)[26]), "=r"((r)[27]), \
          "=r"((r)[28]), "=r"((r)[29]), "=r"((r)[30]), "=r"((r)[31]) \
        : "r"(tmem_addr))

static constexpr uint64_t SMEM_DESC_BASE_SW128 =
    (uint64_t(2) << 61) | (uint64_t(1) << 46) | (uint64_t(64) << 32) | (uint64_t(1) << 16);
#define MAKE_SMEM_DESC(base_addr) (SMEM_DESC_BASE_SW128 | ((uint64_t)((base_addr) >> 4) & 0x3FFF))

__device__ __forceinline__ void tma_load_2d(uint32_t smem_addr, const void* map,
                                            int cx, int cy, uint32_t mbar) {
    asm volatile(
        "cp.async.bulk.tensor.2d.shared::cta.global.tile.mbarrier::complete_tx::bytes "
        "[%0], [%1, {%2, %3}], [%4];"
        :: "r"(smem_addr), "l"(map), "r"(cx), "r"(cy), "r"(mbar) : "memory");
}
__device__ __forceinline__ void tma_load_2d_mc(uint32_t smem_addr, const void* map,
                                               int cx, int cy, uint32_t mbar, uint16_t mask) {
    asm volatile(
        "cp.async.bulk.tensor.2d.shared::cluster.global.tile.mbarrier::complete_tx::bytes.multicast::cluster "
        "[%0], [%1, {%2, %3}], [%4], %5;"
        :: "r"(smem_addr), "l"(map), "r"(cx), "r"(cy), "r"(mbar), "h"(mask) : "memory");
}

__device__ __forceinline__ void mma_mxf8_ss(uint32_t d_tmem, uint64_t a_desc, uint64_t b_desc,
                                            uint32_t idesc, uint32_t sfa, uint32_t sfb, bool acc) {
    uint32_t en = acc ? 1u : 0u;
    asm volatile(
        "{\n\t.reg .pred p;\n\t"
        "setp.ne.u32 p, %6, 0;\n\t"
        "tcgen05.mma.cta_group::1.kind::mxf8f6f4.block_scale.scale_vec::1X "
        "[%0], %1, %2, %3, [%4], [%5], p;\n\t}"
        :: "r"(d_tmem), "l"(a_desc), "l"(b_desc), "r"(idesc),
           "r"(sfa), "r"(sfb), "r"(en) : "memory");
}
#else  // legacy helpers
__device__ __forceinline__ void ldsm_x4(uint32_t* r, uint32_t addr) {
    asm volatile("ldmatrix.sync.aligned.m8n8.x4.shared.b16 {%0,%1,%2,%3}, [%4];"
        : "=r"(r[0]), "=r"(r[1]), "=r"(r[2]), "=r"(r[3]) : "r"(addr));
}
__device__ __forceinline__ void ldsm_x2(uint32_t* r, uint32_t addr) {
    asm volatile("ldmatrix.sync.aligned.m8n8.x2.shared.b16 {%0,%1}, [%2];"
        : "=r"(r[0]), "=r"(r[1]) : "r"(addr));
}
__device__ __forceinline__ void mma_s8(int* c, const uint32_t* a, const uint32_t* b) {
    asm volatile("mma.sync.aligned.m16n8k32.row.col.s32.s8.s8.s32 "
        "{%0,%1,%2,%3}, {%4,%5,%6,%7}, {%8,%9}, {%0,%1,%2,%3};"
        : "+r"(c[0]), "+r"(c[1]), "+r"(c[2]), "+r"(c[3])
        : "r"(a[0]), "r"(a[1]), "r"(a[2]), "r"(a[3]), "r"(b[0]), "r"(b[1]));
}
__device__ __forceinline__ void cp_async16(uint32_t dst, const void* src) {
    asm volatile("cp.async.cg.shared.global [%0], [%1], 16;" :: "r"(dst), "l"(src));
}
#endif

// ============================================================================
// Binarize: fused input+weight, 4x LDG.128 MLP per thread, 1x STG.128.
// tcgen05 pass emits e4m3 (+1=0x38,-1=0xB8,0=0); fallback emits s8.
// ============================================================================
__device__ __forceinline__ unsigned char sign_byte(float x) {
#if USE_TCGEN05
    return (x == 0.0f) ? 0u : (unsigned char)(0x38u | ((__float_as_uint(x) >> 24) & 0x80u));
#else
    return (x == 0.0f) ? 0u : ((__float_as_uint(x) & 0x80000000u) ? 0xFFu : 0x01u);
#endif
}
__device__ __forceinline__ uint32_t pack4(float4 v) {
    return (uint32_t)sign_byte(v.x) | ((uint32_t)sign_byte(v.y) << 8) |
           ((uint32_t)sign_byte(v.z) << 16) | ((uint32_t)sign_byte(v.w) << 24);
}

__global__ __launch_bounds__(BIN_THREADS) void binarize_all_kernel(
    const float4* __restrict__ inA, const float4* __restrict__ inW,
    uint4* __restrict__ outA, uint4* __restrict__ outW)
{
    int t = blockIdx.x * BIN_THREADS + threadIdx.x;
    if (t < NT_A) {
        const float4* p = inA + (size_t)t * 4;
        float4 f0 = p[0], f1 = p[1], f2 = p[2], f3 = p[3];   // 4 independent LDG.128
        outA[t] = make_uint4(pack4(f0), pack4(f1), pack4(f2), pack4(f3));
    } else {
        int tw = t - NT_A;
        int row = tw / W_T_PER_ROW;          // 16 elems/thread, 768 threads/row
        if (row < COUT) {
            const float4* p = inW + (size_t)tw * 4;
            float4 f0 = p[0], f1 = p[1], f2 = p[2], f3 = p[3];
            outW[tw] = make_uint4(pack4(f0), pack4(f1), pack4(f2), pack4(f3));
        } else {
            outW[tw] = make_uint4(0, 0, 0, 0);   // padded N rows contribute 0
        }
    }
}

// ============================================================================
// GEMM kernel: tcgen05 mxf8 SS, 4-stage TMA pipeline, cluster-4 B multicast.
// Grid (4, 64), cluster (1,4,1), 256 threads.
// warps 0-3: scale init + epilogue. warp 4: TMA producer. warp 5: MMA.
// ============================================================================
__global__ __launch_bounds__(256, 1) void binary_gemm_kernel(
    float* __restrict__ out,
    const unsigned char* __restrict__ Ag,
    const unsigned char* __restrict__ Wg,
    const __grid_constant__ CUtensorMap tma_a,
    const __grid_constant__ CUtensorMap tma_b)
{
#if USE_TCGEN05
    extern __shared__ char smem[];
    uint32_t sb = smem_u32(smem);
    int tid = threadIdx.x;
    int wid = tid >> 5;
    int lane = tid & 31;
    int nblk = blockIdx.x;
    int mblk = blockIdx.y;
    uint32_t rank = cluster_rank();   // 0..3 within (1,4,1) cluster

    if (wid == 5) TCGEN05_ALLOC(sb + SMEM_TMEM_PTR, TMEM_COLS);
    __syncthreads();
    uint32_t tmem;
    asm volatile("ld.shared.b32 %0, [%1];" : "=r"(tmem) : "r"(sb + SMEM_TMEM_PTR));

    if (tid == 0) {
        for (int s = 0; s < STAGES; s++) {
            MBARRIER_INIT(sb + SMEM_FULL(s), 1);
            MBARRIER_INIT(sb + SMEM_EMPTY(s), CLUSTER_Y);  // all 4 consumers must arrive
        }
        MBARRIER_INIT(sb + SMEM_DONE, 1);
    }

    // Unit scales (ue8m0 0x7F = 1.0)
    if (wid < 4) {
        uint32_t woff = (uint32_t)wid << 21;
        const uint32_t ones = 0x7F7F7F7Fu;
        for (int c = 0; c < 32; c++) {
            TCGEN05_ST_32X32B_X1(tmem + 256 + c + woff, ones);
        }
        TCGEN05_WAIT_ST();
        TCGEN05_FENCE_BEFORE();
    }
    __syncthreads();
    // All cluster CTAs' mbarriers must be live before any multicast TMA/commit
    CLUSTER_SYNC();

    if (wid == 4) {
        // Producer: local A load + multicast B slice (1/4 of tile) to all 4 CTAs
        uint32_t el = elect_one_pred();
        int s = 0, ph = 1;
        for (int it = 0; it < K_ITERS; ++it) {
            MBARRIER_WAIT_PARITY(sb + SMEM_EMPTY(s), ph);
            if (el) {
                uint32_t full = sb + SMEM_FULL(s);
                // 16384 (local A) + 4 x 8192 (multicast slices from all producers)
                MBARRIER_EXPECT_TX(full, STAGE_BYTES);
                uint32_t a_dst = sb + SMEM_DATA + s * STAGE_BYTES;
                tma_load_2d(a_dst, &tma_a, it * K_TILE, mblk * M_TILE, full);
                uint32_t b_dst = a_dst + A_STAGE_BYTES + rank * B_SLICE_BYTES;
                tma_load_2d_mc(b_dst, &tma_b, it * K_TILE,
                               nblk * N_TILE + (int)rank * B_SLICE_ROWS, full,
                               (uint16_t)MCAST_MASK);
            }
            if (++s == STAGES) { s = 0; ph ^= 1; }
        }
    } else if (wid == 5) {
        TCGEN05_FENCE_AFTER();
        uint32_t el = elect_one_pred();
        int s = 0, ph = 0;
        for (int it = 0; it < K_ITERS; ++it) {
            MBARRIER_WAIT_PARITY(sb + SMEM_FULL(s), ph);
            if (el) {
                uint32_t a_base = sb + SMEM_DATA + s * STAGE_BYTES;
                uint64_t ad = MAKE_SMEM_DESC(a_base);
                uint64_t bd = MAKE_SMEM_DESC(a_base + A_STAGE_BYTES);
                #pragma unroll
                for (int k = 0; k < 4; k++) {
                    mma_mxf8_ss(tmem + TMEM_D, ad + k * 2, bd + k * 2, MMA_IDESC,
                                tmem + TMEM_SCA, tmem + TMEM_SCB,
                                !(it == 0 && k == 0));
                }
                // Consumption signal to ALL cluster CTAs' EMPTY(s)
                TCGEN05_COMMIT_MC(sb + SMEM_EMPTY(s), MCAST_MASK);
            }
            if (++s == STAGES) { s = 0; ph ^= 1; }
        }
        if (el) TCGEN05_COMMIT(sb + SMEM_DONE);
    }

    if (wid < 4) {
        MBARRIER_WAIT_PARITY(sb + SMEM_DONE, 0);
        TCGEN05_FENCE_AFTER();

        int m = mblk * M_TILE + wid * 32 + lane;
        float* orow = out + (size_t)m * COUT;
        int nbase = nblk * N_TILE;

        for (int c0 = 0; c0 < N_TILE; c0 += 32) {
            uint32_t r[32];
            TCGEN05_LD_32X32B_X32(r, tmem + TMEM_D + c0);
            TCGEN05_WAIT_LD();
            TCGEN05_FENCE_BEFORE();
            #pragma unroll
            for (int j = 0; j < 32; j += 4) {
                int n = nbase + c0 + j;
                if (n < COUT) {
                    float4 v = make_float4(__uint_as_float(r[j]), __uint_as_float(r[j + 1]),
                                           __uint_as_float(r[j + 2]), __uint_as_float(r[j + 3]));
                    *reinterpret_cast<float4*>(orow + n) = v;
                }
            }
        }
    }

    __syncthreads();
    CLUSTER_SYNC();   // no CTA exits while peers may still touch cluster state
    if (wid == 5) {
        TCGEN05_RELINQUISH();
        TCGEN05_DEALLOC(tmem, TMEM_COLS);
    }
#else
    // ------------------------------------------------------------------
    // Fallback: legacy int8 mma.sync path (unchanged; cluster attr is inert)
    // ------------------------------------------------------------------
    extern __shared__ char smem[];
    uint32_t sb = smem_u32(smem);
    const int tid = threadIdx.x, lane = tid & 31, wid = tid >> 5;
    const int nblk = blockIdx.x, mblk = blockIdx.y;
    const int wm = wid >> 2, wn = wid & 3;

    int c[4][8][4];
    #pragma unroll
    for (int mi = 0; mi < 4; mi++)
        #pragma unroll
        for (int ni = 0; ni < 8; ni++)
            #pragma unroll
            for (int j = 0; j < 4; j++) c[mi][ni][j] = 0;

    auto prefetch = [&](int it, int s) {
        int kb = it * 32;
        #pragma unroll
        for (int t = 0; t < 3; t++) {
            int idx = tid + t * 256;
            uint32_t dst;
            const unsigned char* src;
            if (idx < 256) {
                int r = idx >> 1, ch = idx & 1;
                dst = sb + s * FB_STAGE + (r * 3 + ch) * 16;
                src = Ag + (size_t)(mblk * 128 + r) * K_DIM + kb + ch * 16;
            } else {
                int j = idx - 256;
                int r = j >> 1, ch = j & 1;
                dst = sb + s * FB_STAGE + FB_A_ST + (r * 3 + ch) * 16;
                src = Wg + (size_t)(nblk * 256 + r) * K_DIM + kb + ch * 16;
            }
            cp_async16(dst, src);
        }
        asm volatile("cp.async.commit_group;" ::: "memory");
    };

    prefetch(0, 0);
    for (int it = 0; it < FB_NIT; ++it) {
        __syncthreads();
        if (it + 1 < FB_NIT) {
            prefetch(it + 1, (it + 1) & 1);
            asm volatile("cp.async.wait_group 1;" ::: "memory");
        } else {
            asm volatile("cp.async.wait_group 0;" ::: "memory");
        }
        __syncthreads();

        int s = it & 1;
        uint32_t aB = sb + s * FB_STAGE;
        uint32_t bB = aB + FB_A_ST;

        uint32_t afr[4][4], bfr[8][2];
        #pragma unroll
        for (int mi = 0; mi < 4; mi++) {
            int row = wm * 64 + mi * 16 + (lane & 15);
            int ch = lane >> 4;
            ldsm_x4(afr[mi], aB + (row * 3 + ch) * 16);
        }
        #pragma unroll
        for (int ni = 0; ni < 8; ni++) {
            int row = wn * 64 + ni * 8 + (lane & 7);
            int ch = (lane >> 3) & 1;
            ldsm_x2(bfr[ni], bB + (row * 3 + ch) * 16);
        }
        #pragma unroll
        for (int mi = 0; mi < 4; mi++)
            #pragma unroll
            for (int ni = 0; ni < 8; ni++)
                mma_s8(c[mi][ni], afr[mi], bfr[ni]);
    }

    int g = lane >> 2, tig = lane & 3;
    #pragma unroll
    for (int mi = 0; mi < 4; mi++) {
        int m0 = mblk * 128 + wm * 64 + mi * 16 + g;
        #pragma unroll
        for (int ni = 0; ni < 8; ni++) {
            int n0 = nblk * 256 + wn * 64 + ni * 8 + tig * 2;
            if (n0 < COUT) {
                out[(size_t)m0 * COUT + n0]       = (float)c[mi][ni][0];
                out[(size_t)(m0 + 8) * COUT + n0] = (float)c[mi][ni][2];
            }
            if (n0 + 1 < COUT) {
                out[(size_t)m0 * COUT + n0 + 1]       = (float)c[mi][ni][1];
                out[(size_t)(m0 + 8) * COUT + n0 + 1] = (float)c[mi][ni][3];
            }
        }
    }
#endif
}

// ============================================================================
// Host launch
// ============================================================================
typedef CUresult (*PFN_TMapEncode)(
    CUtensorMap*, CUtensorMapDataType, cuuint32_t, void*,
    const cuuint64_t*, const cuuint64_t*, const cuuint32_t*, const cuuint32_t*,
    CUtensorMapInterleave, CUtensorMapSwizzle, CUtensorMapL2promotion, CUtensorMapFloatOOBfill);

extern "C" void kernel_launch(void* const* d_in, const int* in_sizes, int n_in,
                              void* d_out, int out_size) {
    const float* inp = (const float*)d_in[0];
    const float* wgt = (const float*)d_in[1];
    if (in_sizes[0] == COUT * K_DIM) { inp = (const float*)d_in[1]; wgt = (const float*)d_in[0]; }
    float* out = (float*)d_out;

    void* pA = nullptr;
    void* pW = nullptr;
    cudaGetSymbolAddress(&pA, g_A);
    cudaGetSymbolAddress(&pW, g_W);

    // 1) fused binarize (input + weight)
    binarize_all_kernel<<<BIN_BLOCKS, BIN_THREADS>>>(
        (const float4*)inp, (const float4*)wgt, (uint4*)pA, (uint4*)pW);

    // 2) TMA descriptors
    PFN_TMapEncode enc = nullptr;
    {
        void* fp = nullptr;
        cudaDriverEntryPointQueryResult st;
        cudaGetDriverEntryPointByVersion("cuTensorMapEncodeTiled", &fp, 12000,
                                         cudaEnableDefault, &st);
        enc = (PFN_TMapEncode)fp;
    }

    CUtensorMap mapA, mapB;
    if (enc) {
        {
            cuuint64_t dims[2] = {K_DIM, BROWS};
            cuuint64_t str[1] = {K_DIM};
            cuuint32_t box[2] = {K_TILE, M_TILE};
            cuuint32_t es[2] = {1, 1};
            enc(&mapA, CU_TENSOR_MAP_DATA_TYPE_UINT8, 2, pA, dims, str, box, es,
                CU_TENSOR_MAP_INTERLEAVE_NONE, CU_TENSOR_MAP_SWIZZLE_128B,
                CU_TENSOR_MAP_L2_PROMOTION_L2_128B, CU_TENSOR_MAP_FLOAT_OOB_FILL_NONE);
        }
        {
            cuuint64_t dims[2] = {K_DIM, CPAD};
            cuuint64_t str[1] = {K_DIM};
            cuuint32_t box[2] = {K_TILE, B_SLICE_ROWS};   // 64-row multicast slices
            cuuint32_t es[2] = {1, 1};
            enc(&mapB, CU_TENSOR_MAP_DATA_TYPE_UINT8, 2, pW, dims, str, box, es,
                CU_TENSOR_MAP_INTERLEAVE_NONE, CU_TENSOR_MAP_SWIZZLE_128B,
                CU_TENSOR_MAP_L2_PROMOTION_L2_128B, CU_TENSOR_MAP_FLOAT_OOB_FILL_NONE);
        }
    }

    // 3) GEMM with cluster (1,4,1) for B multicast
    cudaFuncSetAttribute(binary_gemm_kernel, cudaFuncAttributeMaxDynamicSharedMemorySize, SMEM_BYTES);

    cudaLaunchConfig_t cfg = {};
    cfg.gridDim = dim3(CPAD / N_TILE, BROWS / M_TILE, 1);  // (4, 64)
    cfg.blockDim = dim3(256, 1, 1);
    cfg.dynamicSmemBytes = SMEM_BYTES;
    cudaLaunchAttribute attrs[1];
    attrs[0].id = cudaLaunchAttributeClusterDimension;
    attrs[0].val.clusterDim.x = 1;
    attrs[0].val.clusterDim.y = CLUSTER_Y;
    attrs[0].val.clusterDim.z = 1;
    cfg.attrs = attrs;
    cfg.numAttrs = 1;
    cudaLaunchKernelEx(&cfg, binary_gemm_kernel, out,
                       (const unsigned char*)pA, (const unsigned char*)pW, mapA, mapB);
}

// round 8
// speedup vs baseline: 1.1492x; 1.0698x over previous
#include <cuda_runtime.h>
#include <cuda.h>
#include <cstdint>
#include <cstdio>

// ============================================================================
// Arch-feature dispatch: tcgen05 only exists in compute_103a/sm_103a passes.
// ============================================================================
#if defined(__CUDA_ARCH__) && (defined(__CUDA_ARCH_FEAT_SM103_ALL) || defined(__CUDA_ARCH_FEAT_SM100_ALL))
#define USE_TCGEN05 1
#else
#define USE_TCGEN05 0
#endif

// ============================================================================
// Problem constants
// ============================================================================
#define K_DIM 12288
#define BROWS 8192
#define COUT  1000
#define CPAD  1024

// GEMM tiling (tcgen05 path). Each CTA now computes TWO M-tiles.
#define M_TILE 128
#define N_TILE 256
#define K_TILE 128
#define STAGES 4
#define K_ITERS (K_DIM / K_TILE)      // 96
#define M_PER_CTA 2                   // two m-tiles per CTA -> grid fits 1 wave
#define A_STAGE_BYTES (M_TILE * K_TILE)               // 16384
#define B_STAGE_BYTES (N_TILE * K_TILE)               // 32768
#define STAGE_BYTES   (A_STAGE_BYTES + B_STAGE_BYTES) // 49152

// Cluster: 4 CTAs along mblk share the B tile via TMA multicast slicing
#define CLUSTER_Y 4
#define B_SLICE_ROWS (N_TILE / CLUSTER_Y)             // 64
#define B_SLICE_BYTES (B_SLICE_ROWS * K_TILE)         // 8192
#define MCAST_MASK 0xFu

// SMEM layout (tcgen05 path)
#define SMEM_TMEM_PTR 0
#define SMEM_FULL(s)  (16 + (s) * 8)
#define SMEM_EMPTY(s) (16 + STAGES * 8 + (s) * 8)
#define SMEM_DONE(t)  (16 + 2 * STAGES * 8 + (t) * 8)
#define SMEM_DATA     1024
#define SMEM_BYTES    (SMEM_DATA + STAGES * STAGE_BYTES)   // 197632

// TMEM layout: two 256-col fp32 accumulators (no scales needed for kind::f8f6f4)
#define TMEM_D(t) ((t) * 256)
#define TMEM_COLS 512

// idesc for kind::f8f6f4 (non-block-scaled): dtype=F32 (bit4), atype=btype=E4M3 (0),
// N>>3 at bits[17:23), M>>4 at bits[24:29). = 0x08400010 for 128x256.
#define MMA_IDESC ((1u << 4) | ((N_TILE / 8u) << 17) | ((M_TILE / 16u) << 24))

// Fallback tiling constants
#define FB_NIT    (K_DIM / 32)
#define FB_A_ST   (128 * 48)
#define FB_STAGE  (FB_A_ST + 256 * 48)

// Binarize constants
#define N4A ((BROWS * K_DIM) / 4)
#define N4W ((CPAD * K_DIM) / 4)
#define NT_A (N4A / 4)
#define NT_W (N4W / 4)
#define NT_TOTAL (NT_A + NT_W)
#define BIN_THREADS 256
#define BIN_BLOCKS (NT_TOTAL / BIN_THREADS)
#define W_T_PER_ROW (K_DIM / 16)

// ============================================================================
// Scratch (alloc-free rule: __device__ globals)
// ============================================================================
__device__ __align__(1024) unsigned char g_A[(size_t)BROWS * K_DIM];
__device__ __align__(1024) unsigned char g_W[(size_t)CPAD * K_DIM];

// ============================================================================
// Generic PTX helpers
// ============================================================================
__device__ __forceinline__ uint32_t smem_u32(const void* p) {
    uint32_t a;
    asm("{ .reg .u64 t; cvta.to.shared.u64 t, %1; cvt.u32.u64 %0, t; }" : "=r"(a) : "l"(p));
    return a;
}

#if USE_TCGEN05
__device__ __forceinline__ uint32_t elect_one_pred() {
    uint32_t p;
    asm volatile("{\n\t.reg .pred p;\n\telect.sync _|p, 0xFFFFFFFF;\n\tselp.b32 %0, 1, 0, p;\n\t}" : "=r"(p));
    return p;
}
__device__ __forceinline__ uint32_t cluster_rank() {
    uint32_t r;
    asm("mov.u32 %0, %%cluster_ctarank;" : "=r"(r));
    return r;
}

#define CLUSTER_SYNC() do { \
    asm volatile("barrier.cluster.arrive.aligned;" ::: "memory"); \
    asm volatile("barrier.cluster.wait.aligned;" ::: "memory"); \
} while (0)

#define MBARRIER_INIT(addr, cnt) \
    asm volatile("mbarrier.init.shared.b64 [%0], %1;" :: "r"((uint32_t)(addr)), "r"((uint32_t)(cnt)) : "memory")
#define MBARRIER_EXPECT_TX(addr, bytes) \
    asm volatile("mbarrier.arrive.expect_tx.shared.b64 _, [%0], %1;" :: "r"((uint32_t)(addr)), "r"((uint32_t)(bytes)) : "memory")

#define MBARRIER_WAIT_PARITY(mbar_smem_addr, phase_parity) do { \
    uint32_t _mbar = (uint32_t)(mbar_smem_addr); \
    uint32_t _parity = (uint32_t)(phase_parity); \
    uint32_t _done; \
    asm volatile( \
        "{\n\t.reg .pred p;\n\t" \
        "mbarrier.try_wait.parity.acquire.cta.shared::cta.b64 p, [%1], %2;\n\t" \
        "selp.b32 %0, 1, 0, p;\n\t}" \
        : "=r"(_done) : "r"(_mbar), "r"(_parity) : "memory"); \
    if (!_done) { \
        asm volatile( \
            "{\n\t.reg .pred P1;\n\t" \
            "WAIT_LOOP_%=:\n\t" \
            "mbarrier.try_wait.parity.acquire.cta.shared::cta.b64 P1, [%0], %1, 0x989680;\n\t" \
            "@P1 bra.uni WAIT_DONE_%=;\n\t" \
            "bra.uni WAIT_LOOP_%=;\n\t" \
            "WAIT_DONE_%=:\n\t}" \
            :: "r"(_mbar), "r"(_parity) : "memory"); \
    } \
} while (0)

#define TCGEN05_ALLOC(smem_addr, n) \
    asm volatile("tcgen05.alloc.cta_group::1.sync.aligned.shared::cta.b32 [%0], %1;" \
                 :: "r"((uint32_t)(smem_addr)), "r"((uint32_t)(n)) : "memory")
#define TCGEN05_DEALLOC(tmem, n) \
    asm volatile("tcgen05.dealloc.cta_group::1.sync.aligned.b32 %0, %1;" :: "r"(tmem), "r"((uint32_t)(n)))
#define TCGEN05_RELINQUISH() \
    asm volatile("tcgen05.relinquish_alloc_permit.cta_group::1.sync.aligned;")
#define TCGEN05_COMMIT(mbar) \
    asm volatile("tcgen05.commit.cta_group::1.mbarrier::arrive::one.shared::cluster.b64 [%0];" \
                 :: "r"((uint32_t)(mbar)) : "memory")
#define TCGEN05_COMMIT_MC(mbar, mask) \
    asm volatile("tcgen05.commit.cta_group::1.mbarrier::arrive::one.shared::cluster.multicast::cluster.b64 [%0], %1;" \
                 :: "r"((uint32_t)(mbar)), "h"((uint16_t)(mask)) : "memory")
#define TCGEN05_WAIT_LD() asm volatile("tcgen05.wait::ld.sync.aligned;" ::: "memory")
#define TCGEN05_FENCE_BEFORE() asm volatile("tcgen05.fence::before_thread_sync;" ::: "memory")
#define TCGEN05_FENCE_AFTER()  asm volatile("tcgen05.fence::after_thread_sync;" ::: "memory")

#define TCGEN05_LD_32X32B_X32(r, tmem_addr) \
    asm volatile( \
        "tcgen05.ld.sync.aligned.32x32b.x32.b32 " \
        "{%0, %1, %2, %3, %4, %5, %6, %7, " \
        " %8, %9, %10, %11, %12, %13, %14, %15, " \
        " %16, %17, %18, %19, %20, %21, %22, %23, " \
        " %24, %25, %26, %27, %28, %29, %30, %31}, [%32];" \
        : "=r"((r)[0]),  "=r"((r)[1]),  "=r"((r)[2]),  "=r"((r)[3]), \
          "=r"((r)[4]),  "=r"((r)[5]),  "=r"((r)[6]),  "=r"((r)[7]), \
          "=r"((r)[8]),  "=r"((r)[9]),  "=r"((r)[10]), "=r"((r)[11]), \
          "=r"((r)[12]), "=r"((r)[13]), "=r"((r)[14]), "=r"((r)[15]), \
          "=r"((r)[16]), "=r"((r)[17]), "=r"((r)[18]), "=r"((r)[19]), \
          "=r"((r)[20]), "=r"((r)[21]), "=r"((r)[22]), "=r"((r)[23]), \
          "=r"((r)[24]), "=r"((r)[25]), "=r"((r)[26]), "=r"((r)[27]), \
          "=r"((r)[28]), "=r"((r)[29]), "=r"((r)[30]), "=r"((r)[31]) \
        : "r"(tmem_addr))

static constexpr uint64_t SMEM_DESC_BASE_SW128 =
    (uint64_t(2) << 61) | (uint64_t(1) << 46) | (uint64_t(64) << 32) | (uint64_t(1) << 16);
#define MAKE_SMEM_DESC(base_addr) (SMEM_DESC_BASE_SW128 | ((uint64_t)((base_addr) >> 4) & 0x3FFF))

__device__ __forceinline__ void tma_load_2d(uint32_t smem_addr, const void* map,
                                            int cx, int cy, uint32_t mbar) {
    asm volatile(
        "cp.async.bulk.tensor.2d.shared::cta.global.tile.mbarrier::complete_tx::bytes "
        "[%0], [%1, {%2, %3}], [%4];"
        :: "r"(smem_addr), "l"(map), "r"(cx), "r"(cy), "r"(mbar) : "memory");
}
__device__ __forceinline__ void tma_load_2d_mc(uint32_t smem_addr, const void* map,
                                               int cx, int cy, uint32_t mbar, uint16_t mask) {
    asm volatile(
        "cp.async.bulk.tensor.2d.shared::cluster.global.tile.mbarrier::complete_tx::bytes.multicast::cluster "
        "[%0], [%1, {%2, %3}], [%4], %5;"
        :: "r"(smem_addr), "l"(map), "r"(cx), "r"(cy), "r"(mbar), "h"(mask) : "memory");
}

// Plain FP8 MMA (no block scaling): kind::f8f6f4
__device__ __forceinline__ void mma_f8_ss(uint32_t d_tmem, uint64_t a_desc, uint64_t b_desc,
                                          uint32_t idesc, bool acc) {
    uint32_t en = acc ? 1u : 0u;
    asm volatile(
        "{\n\t.reg .pred p;\n\t"
        "setp.ne.u32 p, %4, 0;\n\t"
        "tcgen05.mma.cta_group::1.kind::f8f6f4 [%0], %1, %2, %3, p;\n\t}"
        :: "r"(d_tmem), "l"(a_desc), "l"(b_desc), "r"(idesc), "r"(en) : "memory");
}
#else  // legacy helpers
__device__ __forceinline__ void ldsm_x4(uint32_t* r, uint32_t addr) {
    asm volatile("ldmatrix.sync.aligned.m8n8.x4.shared.b16 {%0,%1,%2,%3}, [%4];"
        : "=r"(r[0]), "=r"(r[1]), "=r"(r[2]), "=r"(r[3]) : "r"(addr));
}
__device__ __forceinline__ void ldsm_x2(uint32_t* r, uint32_t addr) {
    asm volatile("ldmatrix.sync.aligned.m8n8.x2.shared.b16 {%0,%1}, [%2];"
        : "=r"(r[0]), "=r"(r[1]) : "r"(addr));
}
__device__ __forceinline__ void mma_s8(int* c, const uint32_t* a, const uint32_t* b) {
    asm volatile("mma.sync.aligned.m16n8k32.row.col.s32.s8.s8.s32 "
        "{%0,%1,%2,%3}, {%4,%5,%6,%7}, {%8,%9}, {%0,%1,%2,%3};"
        : "+r"(c[0]), "+r"(c[1]), "+r"(c[2]), "+r"(c[3])
        : "r"(a[0]), "r"(a[1]), "r"(a[2]), "r"(a[3]), "r"(b[0]), "r"(b[1]));
}
__device__ __forceinline__ void cp_async16(uint32_t dst, const void* src) {
    asm volatile("cp.async.cg.shared.global [%0], [%1], 16;" :: "r"(dst), "l"(src));
}
#endif

// ============================================================================
// Binarize: fused input+weight, 4x LDG.128 (streaming) per thread, 1x STG.128.
// ============================================================================
__device__ __forceinline__ unsigned char sign_byte(float x) {
#if USE_TCGEN05
    return (x == 0.0f) ? 0u : (unsigned char)(0x38u | ((__float_as_uint(x) >> 24) & 0x80u));
#else
    return (x == 0.0f) ? 0u : ((__float_as_uint(x) & 0x80000000u) ? 0xFFu : 0x01u);
#endif
}
__device__ __forceinline__ uint32_t pack4(float4 v) {
    return (uint32_t)sign_byte(v.x) | ((uint32_t)sign_byte(v.y) << 8) |
           ((uint32_t)sign_byte(v.z) << 16) | ((uint32_t)sign_byte(v.w) << 24);
}

__global__ __launch_bounds__(BIN_THREADS) void binarize_all_kernel(
    const float4* __restrict__ inA, const float4* __restrict__ inW,
    uint4* __restrict__ outA, uint4* __restrict__ outW)
{
    int t = blockIdx.x * BIN_THREADS + threadIdx.x;
    if (t < NT_A) {
        const float4* p = inA + (size_t)t * 4;
        float4 f0 = __ldcs(p), f1 = __ldcs(p + 1), f2 = __ldcs(p + 2), f3 = __ldcs(p + 3);
        outA[t] = make_uint4(pack4(f0), pack4(f1), pack4(f2), pack4(f3));
    } else {
        int tw = t - NT_A;
        int row = tw / W_T_PER_ROW;
        if (row < COUT) {
            const float4* p = inW + (size_t)tw * 4;
            float4 f0 = __ldcs(p), f1 = __ldcs(p + 1), f2 = __ldcs(p + 2), f3 = __ldcs(p + 3);
            outW[tw] = make_uint4(pack4(f0), pack4(f1), pack4(f2), pack4(f3));
        } else {
            outW[tw] = make_uint4(0, 0, 0, 0);
        }
    }
}

// ============================================================================
// GEMM kernel: tcgen05 f8f6f4 SS, 4-stage TMA pipeline, cluster-4 B multicast.
// Grid (4, 32), cluster (1,4,1), 256 threads. ONE wave (128 CTAs).
// Each CTA: two M-tiles, D double-buffered in TMEM so the epilogue of tile 0
// overlaps the MMA mainloop of tile 1.
// warps 0-3: epilogue. warp 4: TMA producer. warp 5: MMA.
// ============================================================================
__global__ __launch_bounds__(256, 1) void binary_gemm_kernel(
    float* __restrict__ out,
    const unsigned char* __restrict__ Ag,
    const unsigned char* __restrict__ Wg,
    const __grid_constant__ CUtensorMap tma_a,
    const __grid_constant__ CUtensorMap tma_b)
{
#if USE_TCGEN05
    extern __shared__ char smem[];
    uint32_t sb = smem_u32(smem);
    int tid = threadIdx.x;
    int wid = tid >> 5;
    int lane = tid & 31;
    int nblk = blockIdx.x;
    uint32_t rank = cluster_rank();   // 0..3 within (1,4,1) cluster

    if (wid == 5) TCGEN05_ALLOC(sb + SMEM_TMEM_PTR, TMEM_COLS);
    __syncthreads();
    uint32_t tmem;
    asm volatile("ld.shared.b32 %0, [%1];" : "=r"(tmem) : "r"(sb + SMEM_TMEM_PTR));

    if (tid == 0) {
        for (int s = 0; s < STAGES; s++) {
            MBARRIER_INIT(sb + SMEM_FULL(s), 1);
            MBARRIER_INIT(sb + SMEM_EMPTY(s), CLUSTER_Y);
        }
        MBARRIER_INIT(sb + SMEM_DONE(0), 1);
        MBARRIER_INIT(sb + SMEM_DONE(1), 1);
    }
    __syncthreads();
    CLUSTER_SYNC();   // all cluster CTAs' mbarriers live before multicast ops

    if (wid == 4) {
        // ---- Producer: 192 continuous K-iters over two m-tiles ----
        uint32_t el = elect_one_pred();
        int s = 0, ph = 1;
        for (int t = 0; t < M_PER_CTA; ++t) {
            int mrow = (blockIdx.y * M_PER_CTA + t) * M_TILE;
            for (int it = 0; it < K_ITERS; ++it) {
                MBARRIER_WAIT_PARITY(sb + SMEM_EMPTY(s), ph);
                if (el) {
                    uint32_t full = sb + SMEM_FULL(s);
                    MBARRIER_EXPECT_TX(full, STAGE_BYTES);  // 16K A + 4x8K B slices
                    uint32_t a_dst = sb + SMEM_DATA + s * STAGE_BYTES;
                    tma_load_2d(a_dst, &tma_a, it * K_TILE, mrow, full);
                    uint32_t b_dst = a_dst + A_STAGE_BYTES + rank * B_SLICE_BYTES;
                    tma_load_2d_mc(b_dst, &tma_b, it * K_TILE,
                                   nblk * N_TILE + (int)rank * B_SLICE_ROWS, full,
                                   (uint16_t)MCAST_MASK);
                }
                if (++s == STAGES) { s = 0; ph ^= 1; }
            }
        }
    } else if (wid == 5) {
        // ---- MMA issue: tile t accumulates into TMEM_D(t) ----
        TCGEN05_FENCE_AFTER();
        uint32_t el = elect_one_pred();
        int s = 0, ph = 0;
        for (int t = 0; t < M_PER_CTA; ++t) {
            uint32_t dbase = tmem + TMEM_D(t);
            for (int it = 0; it < K_ITERS; ++it) {
                MBARRIER_WAIT_PARITY(sb + SMEM_FULL(s), ph);
                if (el) {
                    uint32_t a_base = sb + SMEM_DATA + s * STAGE_BYTES;
                    uint64_t ad = MAKE_SMEM_DESC(a_base);
                    uint64_t bd = MAKE_SMEM_DESC(a_base + A_STAGE_BYTES);
                    #pragma unroll
                    for (int k = 0; k < 4; k++) {
                        mma_f8_ss(dbase, ad + k * 2, bd + k * 2, MMA_IDESC,
                                  !(it == 0 && k == 0));
                    }
                    TCGEN05_COMMIT_MC(sb + SMEM_EMPTY(s), MCAST_MASK);
                }
                if (++s == STAGES) { s = 0; ph ^= 1; }
            }
            // Signal tile-t accumulator complete (fires when prior MMAs retire);
            // epilogue of tile t overlaps mainloop of tile t+1.
            if (el) TCGEN05_COMMIT(sb + SMEM_DONE(t));
        }
    }

    if (wid < 4) {
        // ---- Epilogue: per tile, read D from TMEM and store ----
        for (int t = 0; t < M_PER_CTA; ++t) {
            MBARRIER_WAIT_PARITY(sb + SMEM_DONE(t), 0);
            TCGEN05_FENCE_AFTER();

            int m = (blockIdx.y * M_PER_CTA + t) * M_TILE + wid * 32 + lane;
            float* orow = out + (size_t)m * COUT;
            int nbase = nblk * N_TILE;
            uint32_t dbase = tmem + TMEM_D(t);

            for (int c0 = 0; c0 < N_TILE; c0 += 32) {
                uint32_t r[32];
                TCGEN05_LD_32X32B_X32(r, dbase + c0);
                TCGEN05_WAIT_LD();
                TCGEN05_FENCE_BEFORE();
                #pragma unroll
                for (int j = 0; j < 32; j += 4) {
                    int n = nbase + c0 + j;
                    if (n < COUT) {
                        float4 v = make_float4(__uint_as_float(r[j]), __uint_as_float(r[j + 1]),
                                               __uint_as_float(r[j + 2]), __uint_as_float(r[j + 3]));
                        *reinterpret_cast<float4*>(orow + n) = v;
                    }
                }
            }
        }
    }

    __syncthreads();
    CLUSTER_SYNC();
    if (wid == 5) {
        TCGEN05_RELINQUISH();
        TCGEN05_DEALLOC(tmem, TMEM_COLS);
    }
#else
    // ------------------------------------------------------------------
    // Fallback: legacy int8 mma.sync path; now loops over 2 m-tiles to
    // match the (4, 32) grid.
    // ------------------------------------------------------------------
    extern __shared__ char smem[];
    uint32_t sb = smem_u32(smem);
    const int tid = threadIdx.x, lane = tid & 31, wid = tid >> 5;
    const int nblk = blockIdx.x;
    const int wm = wid >> 2, wn = wid & 3;

    for (int t = 0; t < M_PER_CTA; ++t) {
        const int mrow = (blockIdx.y * M_PER_CTA + t) * 128;

        int c[4][8][4];
        #pragma unroll
        for (int mi = 0; mi < 4; mi++)
            #pragma unroll
            for (int ni = 0; ni < 8; ni++)
                #pragma unroll
                for (int j = 0; j < 4; j++) c[mi][ni][j] = 0;

        auto prefetch = [&](int it, int s) {
            int kb = it * 32;
            #pragma unroll
            for (int tt = 0; tt < 3; tt++) {
                int idx = tid + tt * 256;
                uint32_t dst;
                const unsigned char* src;
                if (idx < 256) {
                    int r = idx >> 1, ch = idx & 1;
                    dst = sb + s * FB_STAGE + (r * 3 + ch) * 16;
                    src = Ag + (size_t)(mrow + r) * K_DIM + kb + ch * 16;
                } else {
                    int j = idx - 256;
                    int r = j >> 1, ch = j & 1;
                    dst = sb + s * FB_STAGE + FB_A_ST + (r * 3 + ch) * 16;
                    src = Wg + (size_t)(nblk * 256 + r) * K_DIM + kb + ch * 16;
                }
                cp_async16(dst, src);
            }
            asm volatile("cp.async.commit_group;" ::: "memory");
        };

        prefetch(0, 0);
        for (int it = 0; it < FB_NIT; ++it) {
            __syncthreads();
            if (it + 1 < FB_NIT) {
                prefetch(it + 1, (it + 1) & 1);
                asm volatile("cp.async.wait_group 1;" ::: "memory");
            } else {
                asm volatile("cp.async.wait_group 0;" ::: "memory");
            }
            __syncthreads();

            int s = it & 1;
            uint32_t aB = sb + s * FB_STAGE;
            uint32_t bB = aB + FB_A_ST;

            uint32_t afr[4][4], bfr[8][2];
            #pragma unroll
            for (int mi = 0; mi < 4; mi++) {
                int row = wm * 64 + mi * 16 + (lane & 15);
                int ch = lane >> 4;
                ldsm_x4(afr[mi], aB + (row * 3 + ch) * 16);
            }
            #pragma unroll
            for (int ni = 0; ni < 8; ni++) {
                int row = wn * 64 + ni * 8 + (lane & 7);
                int ch = (lane >> 3) & 1;
                ldsm_x2(bfr[ni], bB + (row * 3 + ch) * 16);
            }
            #pragma unroll
            for (int mi = 0; mi < 4; mi++)
                #pragma unroll
                for (int ni = 0; ni < 8; ni++)
                    mma_s8(c[mi][ni], afr[mi], bfr[ni]);
        }
        __syncthreads();

        int g = lane >> 2, tig = lane & 3;
        #pragma unroll
        for (int mi = 0; mi < 4; mi++) {
            int m0 = mrow + wm * 64 + mi * 16 + g;
            #pragma unroll
            for (int ni = 0; ni < 8; ni++) {
                int n0 = nblk * 256 + wn * 64 + ni * 8 + tig * 2;
                if (n0 < COUT) {
                    out[(size_t)m0 * COUT + n0]       = (float)c[mi][ni][0];
                    out[(size_t)(m0 + 8) * COUT + n0] = (float)c[mi][ni][2];
                }
                if (n0 + 1 < COUT) {
                    out[(size_t)m0 * COUT + n0 + 1]       = (float)c[mi][ni][1];
                    out[(size_t)(m0 + 8) * COUT + n0 + 1] = (float)c[mi][ni][3];
                }
            }
        }
        __syncthreads();
    }
#endif
}

// ============================================================================
// Host launch
// ============================================================================
typedef CUresult (*PFN_TMapEncode)(
    CUtensorMap*, CUtensorMapDataType, cuuint32_t, void*,
    const cuuint64_t*, const cuuint64_t*, const cuuint32_t*, const cuuint32_t*,
    CUtensorMapInterleave, CUtensorMapSwizzle, CUtensorMapL2promotion, CUtensorMapFloatOOBfill);

extern "C" void kernel_launch(void* const* d_in, const int* in_sizes, int n_in,
                              void* d_out, int out_size) {
    const float* inp = (const float*)d_in[0];
    const float* wgt = (const float*)d_in[1];
    if (in_sizes[0] == COUT * K_DIM) { inp = (const float*)d_in[1]; wgt = (const float*)d_in[0]; }
    float* out = (float*)d_out;

    void* pA = nullptr;
    void* pW = nullptr;
    cudaGetSymbolAddress(&pA, g_A);
    cudaGetSymbolAddress(&pW, g_W);

    // 1) fused binarize (input + weight)
    binarize_all_kernel<<<BIN_BLOCKS, BIN_THREADS>>>(
        (const float4*)inp, (const float4*)wgt, (uint4*)pA, (uint4*)pW);

    // 2) TMA descriptors
    PFN_TMapEncode enc = nullptr;
    {
        void* fp = nullptr;
        cudaDriverEntryPointQueryResult st;
        cudaGetDriverEntryPointByVersion("cuTensorMapEncodeTiled", &fp, 12000,
                                         cudaEnableDefault, &st);
        enc = (PFN_TMapEncode)fp;
    }

    CUtensorMap mapA, mapB;
    if (enc) {
        {
            cuuint64_t dims[2] = {K_DIM, BROWS};
            cuuint64_t str[1] = {K_DIM};
            cuuint32_t box[2] = {K_TILE, M_TILE};
            cuuint32_t es[2] = {1, 1};
            enc(&mapA, CU_TENSOR_MAP_DATA_TYPE_UINT8, 2, pA, dims, str, box, es,
                CU_TENSOR_MAP_INTERLEAVE_NONE, CU_TENSOR_MAP_SWIZZLE_128B,
                CU_TENSOR_MAP_L2_PROMOTION_L2_128B, CU_TENSOR_MAP_FLOAT_OOB_FILL_NONE);
        }
        {
            cuuint64_t dims[2] = {K_DIM, CPAD};
            cuuint64_t str[1] = {K_DIM};
            cuuint32_t box[2] = {K_TILE, B_SLICE_ROWS};
            cuuint32_t es[2] = {1, 1};
            enc(&mapB, CU_TENSOR_MAP_DATA_TYPE_UINT8, 2, pW, dims, str, box, es,
                CU_TENSOR_MAP_INTERLEAVE_NONE, CU_TENSOR_MAP_SWIZZLE_128B,
                CU_TENSOR_MAP_L2_PROMOTION_L2_128B, CU_TENSOR_MAP_FLOAT_OOB_FILL_NONE);
        }
    }

    // 3) GEMM: grid (4, 32) = 128 CTAs (one wave), cluster (1,4,1)
    cudaFuncSetAttribute(binary_gemm_kernel, cudaFuncAttributeMaxDynamicSharedMemorySize, SMEM_BYTES);

    cudaLaunchConfig_t cfg = {};
    cfg.gridDim = dim3(CPAD / N_TILE, BROWS / (M_TILE * M_PER_CTA), 1);  // (4, 32)
    cfg.blockDim = dim3(256, 1, 1);
    cfg.dynamicSmemBytes = SMEM_BYTES;
    cudaLaunchAttribute attrs[1];
    attrs[0].id = cudaLaunchAttributeClusterDimension;
    attrs[0].val.clusterDim.x = 1;
    attrs[0].val.clusterDim.y = CLUSTER_Y;
    attrs[0].val.clusterDim.z = 1;
    cfg.attrs = attrs;
    cfg.numAttrs = 1;
    cudaLaunchKernelEx(&cfg, binary_gemm_kernel, out,
                       (const unsigned char*)pA, (const unsigned char*)pW, mapA, mapB);
}